// round 1
// baseline (speedup 1.0000x reference)
#include <cuda_runtime.h>
#include <cuda_bf16.h>

// Morphology dilation2d, diamond 5x5, depthwise, C=3, N=32, H=W=512.
// out(y,x) = 1.0 iff ANY input in the diamond neighborhood is > 0, else 0.0.
// (Sum of nonnegative floats > 0 <=> some term > 0, so this is bit-exact vs
// the conv+threshold reference.)

#define IMG_W 512
#define IMG_H 512
#define N_IMGS 96      // 32 * 3 (batch * channels), all independent planes
#define STRIP 32       // output rows per block

__global__ __launch_bounds__(128, 8)
void dilate_diamond5_kernel(const float* __restrict__ x, float* __restrict__ out) {
    const int img = blockIdx.y;
    const int y0  = blockIdx.x * STRIP;
    const int tid = threadIdx.x;          // 0..127, each owns 4 columns
    const int x0  = tid << 2;             // column base (0..508)

    const float* __restrict__ in = x   + (size_t)img * IMG_H * IMG_W;
    float* __restrict__       op = out + (size_t)img * IMG_H * IMG_W;

    // Rolling ring of per-row horizontal OR masks (4 output columns each):
    //   H1[r] bit j = p(x0+j)                (width-1 row OR)
    //   H3[r] bit j = OR p(x0+j-1..x0+j+1)  (width-3)
    //   H5[r] bit j = OR p(x0+j-2..x0+j+2)  (width-5)
    unsigned H1[5], H3[5], H5[5];
#pragma unroll
    for (int i = 0; i < 5; ++i) { H1[i] = 0u; H3[i] = 0u; H5[i] = 0u; }

    const bool has_left  = (tid > 0);
    const bool has_right = (tid < 127);

#pragma unroll
    for (int i = 0; i < STRIP + 4; ++i) {
        const int y = y0 - 2 + i;
        unsigned m = 0u;  // bits 2..9 = predicate of columns x0-2 .. x0+5
        if (y >= 0 && y < IMG_H) {
            const float* __restrict__ row = in + (size_t)y * IMG_W;
            float4 B = *reinterpret_cast<const float4*>(row + x0);
            float az = 0.f, aw = 0.f, cx = 0.f, cy = 0.f;
            if (has_left) {
                float4 A = *reinterpret_cast<const float4*>(row + x0 - 4);
                az = A.z; aw = A.w;
            }
            if (has_right) {
                float4 C = *reinterpret_cast<const float4*>(row + x0 + 4);
                cx = C.x; cy = C.y;
            }
            m  = (az  > 0.f) ? 0x004u : 0u;   // bit 2 : x0-2
            m |= (aw  > 0.f) ? 0x008u : 0u;   // bit 3 : x0-1
            m |= (B.x > 0.f) ? 0x010u : 0u;   // bit 4 : x0
            m |= (B.y > 0.f) ? 0x020u : 0u;   // bit 5 : x0+1
            m |= (B.z > 0.f) ? 0x040u : 0u;   // bit 6 : x0+2
            m |= (B.w > 0.f) ? 0x080u : 0u;   // bit 7 : x0+3
            m |= (cx  > 0.f) ? 0x100u : 0u;   // bit 8 : x0+4
            m |= (cy  > 0.f) ? 0x200u : 0u;   // bit 9 : x0+5
        }
        // Row-wise OR collapses:
        unsigned t3 = m | (m >> 1) | (m >> 2);         // bit j+3 = OR bits j+3..j+5
        unsigned t5 = t3 | (m >> 3) | (m >> 4);        // bit j+2 = OR bits j+2..j+6
        const int s = i % 5;
        H1[s] = (m  >> 4) & 0xFu;
        H3[s] = (t3 >> 3) & 0xFu;
        H5[s] = (t5 >> 2) & 0xFu;

        if (i >= 4) {
            const int yo = y - 2;   // output row (in [y0, y0+STRIP))
            // diamond = h1(yo-2) | h3(yo-1) | h5(yo) | h3(yo+1) | h1(yo+2)
            unsigned o = H1[(i - 4) % 5] | H3[(i - 3) % 5] | H5[(i - 2) % 5]
                       | H3[(i - 1) % 5] | H1[s];
            float4 r;
            r.x = (o & 1u) ? 1.f : 0.f;
            r.y = (o & 2u) ? 1.f : 0.f;
            r.z = (o & 4u) ? 1.f : 0.f;
            r.w = (o & 8u) ? 1.f : 0.f;
            *reinterpret_cast<float4*>(op + (size_t)yo * IMG_W + x0) = r;
        }
    }
}

extern "C" void kernel_launch(void* const* d_in, const int* in_sizes, int n_in,
                              void* d_out, int out_size) {
    (void)in_sizes; (void)n_in; (void)out_size;
    const float* x = (const float*)d_in[0];
    // d_in[1] (the diamond weight) is implied by the fixed structuring element.
    float* out = (float*)d_out;
    dim3 grid(IMG_H / STRIP, N_IMGS);
    dilate_diamond5_kernel<<<grid, 128>>>(x, out);
}